// round 5
// baseline (speedup 1.0000x reference)
#include <cuda_runtime.h>

#define NTN 500000
#define NCN 100000
#define NMN 20000
#define NE  500000
#define FIN 128
#define FHID 64

// ---------------- device scratch ----------------
__device__ float g_agg_c[NCN * FIN];
__device__ float g_agg_m[NMN * FIN];
__device__ float g_p_c[NCN * 2];
__device__ float g_p_m[NMN * 2];
__device__ int   g_cnt_t2c[NCN];
__device__ int   g_cnt_t2m[NMN];
__device__ int   g_cnt_c2t[NTN];
__device__ int   g_cnt_m2t[NTN];
__device__ int   g_off_c[NCN];
__device__ int   g_off_m[NMN];
__device__ int   g_cur_c[NCN];
__device__ int   g_cur_m[NMN];
__device__ int   g_eid_c[NE];     // src node id per CSR slot (t2c)
__device__ int   g_eid_m[NE];     // src node id per CSR slot (t2m)
__device__ float g_M_c[FHID * 2];
__device__ float g_M_m[FHID * 2];
__device__ float g_b2_c[2];
__device__ float g_b2_m[2];

// ---------------- kernels ----------------

__global__ void zero_kernel() {
    int i = blockIdx.x * blockDim.x + threadIdx.x;
    int stride = gridDim.x * blockDim.x;
    for (int j = i; j < NCN; j += stride) { g_cnt_t2c[j] = 0; g_cur_c[j] = 0; }
    for (int j = i; j < NMN; j += stride) { g_cnt_t2m[j] = 0; g_cur_m[j] = 0; }
    for (int j = i; j < NTN; j += stride) { g_cnt_c2t[j] = 0; g_cnt_m2t[j] = 0; }
}

template <int W>
__global__ void count_kernel(const int* __restrict__ dst) {
    int i = blockIdx.x * blockDim.x + threadIdx.x;
    if (i >= NE) return;
    int* cnt = (W == 0) ? g_cnt_t2c : (W == 1) ? g_cnt_t2m : (W == 2) ? g_cnt_c2t : g_cnt_m2t;
    atomicAdd(&cnt[dst[i]], 1);
}

// Single-block exclusive prefix scan, int4-vectorized (n % 4 == 0). 1024 threads.
// Pointers resolved device-side (template W) — device globals must NOT be
// passed as host-side kernel args.
template <int W>
__global__ void scan_kernel() {
    const int* cnt = W ? g_cnt_t2m : g_cnt_t2c;
    int*       off = W ? g_off_m : g_off_c;
    const int  n   = W ? NMN : NCN;

    __shared__ int wsum[32];
    __shared__ int carry;
    int t = threadIdx.x;
    if (t == 0) carry = 0;
    __syncthreads();
    for (int base = 0; base < n; base += 4096) {
        int i = base + t * 4;
        int4 v = make_int4(0, 0, 0, 0);
        if (i < n) v = ((const int4*)cnt)[i >> 2];
        int s0 = v.x, s1 = s0 + v.y, s2 = s1 + v.z, s3 = s2 + v.w;
        int x = s3;
        #pragma unroll
        for (int o = 1; o < 32; o <<= 1) {
            int y = __shfl_up_sync(0xffffffffu, x, o);
            if ((t & 31) >= o) x += y;
        }
        if ((t & 31) == 31) wsum[t >> 5] = x;
        __syncthreads();
        if (t < 32) {
            int w = wsum[t], xs = w;
            #pragma unroll
            for (int o = 1; o < 32; o <<= 1) {
                int y = __shfl_up_sync(0xffffffffu, xs, o);
                if (t >= o) xs += y;
            }
            wsum[t] = xs - w;   // exclusive across warps
        }
        __syncthreads();
        int excl = carry + wsum[t >> 5] + (x - s3);
        if (i < n) {
            int4 o4;
            o4.x = excl; o4.y = excl + s0; o4.z = excl + s1; o4.w = excl + s2;
            ((int4*)off)[i >> 2] = o4;
        }
        __syncthreads();
        if (t == 1023) carry += wsum[31] + x;   // excl-prefix of warp31 + its inclusive sum
        __syncthreads();
    }
}

template <int W>
__global__ void fill_kernel(const int* __restrict__ src, const int* __restrict__ dst) {
    int e = blockIdx.x * blockDim.x + threadIdx.x;
    if (e >= NE) return;
    const int* off = W ? g_off_m : g_off_c;
    int* cur = W ? g_cur_m : g_cur_c;
    int* eid = W ? g_eid_m : g_eid_c;
    int d = dst[e];
    int p = atomicAdd(&cur[d], 1);
    eid[off[d] + p] = src[e];
}

// Gather-side aggregation: one warp per dst node, lane covers one float4 of the row.
template <int W>
__global__ void agg_kernel(const float* __restrict__ feat) {
    int g = blockIdx.x * blockDim.x + threadIdx.x;
    int warp = g >> 5;
    int lane = g & 31;
    int n = W ? NMN : NCN;
    if (warp >= n) return;
    const int* off = W ? g_off_m : g_off_c;
    const int* cnt = W ? g_cnt_t2m : g_cnt_t2c;
    const int* eid = W ? g_eid_m : g_eid_c;
    float* agg = W ? g_agg_m : g_agg_c;

    int o = off[warp], c = cnt[warp];
    float4 acc = make_float4(0.f, 0.f, 0.f, 0.f);
    for (int b = 0; b < c; b += 32) {
        int m = min(32, c - b);
        int sreg = (lane < m) ? eid[o + b + lane] : 0;
        for (int j = 0; j < m; j++) {
            int s = __shfl_sync(0xffffffffu, sreg, j);
            float4 v = __ldg((const float4*)feat + (size_t)s * (FIN / 4) + lane);
            acc.x += v.x; acc.y += v.y; acc.z += v.z; acc.w += v.w;
        }
    }
    ((float4*)agg)[(size_t)warp * (FIN / 4) + lane] = acc;
}

__global__ void make_M_kernel(const float* __restrict__ W1c, const float* __restrict__ b1c,
                              const float* __restrict__ W1m, const float* __restrict__ b1m,
                              const float* __restrict__ Wf) {
    int t = threadIdx.x;  // 256 threads
    if (t < 128) {
        int k = t >> 1, o = t & 1;
        float s = 0.f;
        #pragma unroll
        for (int j = 0; j < FHID; j++) s += W1c[k * FHID + j] * Wf[j * 2 + o];
        g_M_c[k * 2 + o] = s;
    } else {
        int tt = t - 128;
        int k = tt >> 1, o = tt & 1;
        float s = 0.f;
        #pragma unroll
        for (int j = 0; j < FHID; j++) s += W1m[k * FHID + j] * Wf[j * 2 + o];
        g_M_m[k * 2 + o] = s;
    }
    if (t < 2) {
        float s = 0.f;
        #pragma unroll
        for (int j = 0; j < FHID; j++) s += b1c[j] * Wf[j * 2 + t];
        g_b2_c[t] = s;
    } else if (t < 4) {
        int o = t - 2;
        float s = 0.f;
        #pragma unroll
        for (int j = 0; j < FHID; j++) s += b1m[j] * Wf[j * 2 + o];
        g_b2_m[o] = s;
    }
}

// Per-dst-node: h0 = lrelu((agg/cnt)@W0 + b0) [0 if cnt==0], p = h0 @ M + b2.
template <int W>
__global__ void layer0_kernel(const float* __restrict__ W0, const float* __restrict__ b0) {
    __shared__ float sW[FIN * FHID];
    __shared__ float sA[16 * 129];

    const float* agg = W ? g_agg_m : g_agg_c;
    const int*   cnt = W ? g_cnt_t2m : g_cnt_t2c;
    const float* M   = W ? g_M_m : g_M_c;
    const float* b2  = W ? g_b2_m : g_b2_c;
    float*       pout = W ? g_p_m : g_p_c;

    int t = threadIdx.x;
    int base = blockIdx.x * 16;

    float4* sW4w = (float4*)sW;
    const float4* W04 = (const float4*)W0;
    for (int i = t; i < FIN * FHID / 4; i += 128) sW4w[i] = W04[i];
    for (int i = t; i < 16 * FIN; i += 128) {
        int n = i >> 7, k = i & 127;
        sA[n * 129 + k] = agg[(size_t)(base + n) * FIN + k];
    }
    __syncthreads();

    int n = t >> 3;
    int cg = t & 7;
    float acc[8] = {0.f, 0.f, 0.f, 0.f, 0.f, 0.f, 0.f, 0.f};
    const float4* sW4 = (const float4*)sW;
    #pragma unroll 4
    for (int k = 0; k < FIN; k++) {
        float a = sA[n * 129 + k];
        float4 w0 = sW4[k * 16 + cg * 2];
        float4 w1 = sW4[k * 16 + cg * 2 + 1];
        acc[0] += a * w0.x; acc[1] += a * w0.y; acc[2] += a * w0.z; acc[3] += a * w0.w;
        acc[4] += a * w1.x; acc[5] += a * w1.y; acc[6] += a * w1.z; acc[7] += a * w1.w;
    }

    int node = base + n;
    int c = cnt[node];
    float p0 = 0.f, p1 = 0.f;
    if (c > 0) {
        float inv = 1.f / (float)c;
        #pragma unroll
        for (int j = 0; j < 8; j++) {
            int col = cg * 8 + j;
            float h = acc[j] * inv + b0[col];
            h = (h > 0.f) ? h : 0.01f * h;
            p0 += h * M[col * 2];
            p1 += h * M[col * 2 + 1];
        }
    }
    #pragma unroll
    for (int off = 4; off; off >>= 1) {
        p0 += __shfl_down_sync(0xffffffffu, p0, off, 8);
        p1 += __shfl_down_sync(0xffffffffu, p1, off, 8);
    }
    if (cg == 0) {
        pout[node * 2]     = p0 + b2[0];
        pout[node * 2 + 1] = p1 + b2[1];
    }
}

__global__ void out_init_kernel(float* __restrict__ out, const float* __restrict__ bf) {
    int i = blockIdx.x * blockDim.x + threadIdx.x;
    if (i < NTN) ((float2*)out)[i] = make_float2(bf[0], bf[1]);
}

template <int W>
__global__ void scatter_out_kernel(const int* __restrict__ src, const int* __restrict__ dst,
                                   float* __restrict__ out) {
    int e = blockIdx.x * blockDim.x + threadIdx.x;
    if (e >= NE) return;
    int s = src[e], d = dst[e];
    const float* p   = W ? g_p_m : g_p_c;
    const int*   cnt = W ? g_cnt_m2t : g_cnt_c2t;
    float inv = 1.f / (float)cnt[d];
    float a = p[2 * s] * inv;
    float b = p[2 * s + 1] * inv;
    float* ap = out + 2 * (size_t)d;
    asm volatile("red.global.add.v2.f32 [%0], {%1,%2};"
                 :: "l"(ap), "f"(a), "f"(b) : "memory");
}

// ---------------- launch ----------------
extern "C" void kernel_launch(void* const* d_in, const int* in_sizes, int n_in,
                              void* d_out, int out_size) {
    const float* feat    = (const float*)d_in[0];
    const int* src_c2t   = (const int*)d_in[3];
    const int* dst_c2t   = (const int*)d_in[4];
    const int* src_m2t   = (const int*)d_in[5];
    const int* dst_m2t   = (const int*)d_in[6];
    const int* src_t2c   = (const int*)d_in[7];
    const int* dst_t2c   = (const int*)d_in[8];
    const int* src_t2m   = (const int*)d_in[9];
    const int* dst_t2m   = (const int*)d_in[10];
    const float* W1_c2t  = (const float*)d_in[13];
    const float* b1_c2t  = (const float*)d_in[14];
    const float* W1_m2t  = (const float*)d_in[17];
    const float* b1_m2t  = (const float*)d_in[18];
    const float* W0_t2c  = (const float*)d_in[19];
    const float* b0_t2c  = (const float*)d_in[20];
    const float* W0_t2m  = (const float*)d_in[23];
    const float* b0_t2m  = (const float*)d_in[24];
    const float* Wf      = (const float*)d_in[27];
    const float* bf      = (const float*)d_in[28];
    float* out = (float*)d_out;

    const int TB = 256;
    const int EB = (NE + TB - 1) / TB;

    zero_kernel<<<1024, TB>>>();
    count_kernel<0><<<EB, TB>>>(dst_t2c);
    count_kernel<1><<<EB, TB>>>(dst_t2m);
    count_kernel<2><<<EB, TB>>>(dst_c2t);
    count_kernel<3><<<EB, TB>>>(dst_m2t);
    make_M_kernel<<<1, 256>>>(W1_c2t, b1_c2t, W1_m2t, b1_m2t, Wf);

    // CSR build for t2c / t2m (globals resolved device-side)
    scan_kernel<0><<<1, 1024>>>();
    scan_kernel<1><<<1, 1024>>>();
    fill_kernel<0><<<EB, TB>>>(src_t2c, dst_t2c);
    fill_kernel<1><<<EB, TB>>>(src_t2m, dst_t2m);

    // gather-side aggregation (atomic-free)
    agg_kernel<0><<<(NCN * 32 + TB - 1) / TB, TB>>>(feat);
    agg_kernel<1><<<(NMN * 32 + TB - 1) / TB, TB>>>(feat);

    layer0_kernel<0><<<NCN / 16, 128>>>(W0_t2c, b0_t2c);
    layer0_kernel<1><<<NMN / 16, 128>>>(W0_t2m, b0_t2m);

    out_init_kernel<<<(NTN + TB - 1) / TB, TB>>>(out, bf);
    scatter_out_kernel<0><<<EB, TB>>>(src_c2t, dst_c2t, out);
    scatter_out_kernel<1><<<EB, TB>>>(src_m2t, dst_m2t, out);
}

// round 6
// speedup vs baseline: 1.7298x; 1.7298x over previous
#include <cuda_runtime.h>

#define NTN 500000
#define NCN 100000
#define NMN 20000
#define NE  500000
#define FIN 128
#define FHID 64

#define NCHC 25          // ceil(NCN/4096)
#define NCHM 5           // ceil(NMN/4096)
#define NBC 1563         // ceil(NCN/64)
#define NBM 313          // ceil(NMN/64)

// ---------------- device scratch ----------------
__device__ float g_agg_c[NCN * FIN];
__device__ float g_agg_m[NMN * FIN];
__device__ float g_p_c[NCN * 2];
__device__ float g_p_m[NMN * 2];
__device__ int   g_cnt_t2c[NCN];
__device__ int   g_cnt_t2m[NMN];
__device__ int   g_cnt_c2t[NTN];
__device__ int   g_cnt_m2t[NTN];
__device__ int   g_off_c[NCN];
__device__ int   g_off_m[NMN];
__device__ int   g_cur_c[NCN];
__device__ int   g_cur_m[NMN];
__device__ int   g_eid_c[NE];
__device__ int   g_eid_m[NE];
__device__ int   g_csum[NCHC + NCHM];
__device__ int   g_cbase[NCHC + NCHM];
__device__ float g_M_c[FHID * 2];
__device__ float g_M_m[FHID * 2];
__device__ float g_b2_c[2];
__device__ float g_b2_m[2];

// ---------------- kernels ----------------

__global__ void init_kernel() {
    int i = blockIdx.x * blockDim.x + threadIdx.x;
    int stride = gridDim.x * blockDim.x;
    for (int j = i; j < NCN; j += stride) { g_cnt_t2c[j] = 0; g_cur_c[j] = 0; }
    for (int j = i; j < NMN; j += stride) { g_cnt_t2m[j] = 0; g_cur_m[j] = 0; }
    for (int j = i; j < NTN; j += stride) { g_cnt_c2t[j] = 0; g_cnt_m2t[j] = 0; }
}

// All 4 relations in one launch.
__global__ void count_all_kernel(const int* __restrict__ d_t2c, const int* __restrict__ d_t2m,
                                 const int* __restrict__ d_c2t, const int* __restrict__ d_m2t) {
    int i = blockIdx.x * blockDim.x + threadIdx.x;
    if (i >= 4 * NE) return;
    int r = i / NE, e = i - r * NE;
    if (r == 0)      atomicAdd(&g_cnt_t2c[d_t2c[e]], 1);
    else if (r == 1) atomicAdd(&g_cnt_t2m[d_t2m[e]], 1);
    else if (r == 2) atomicAdd(&g_cnt_c2t[d_c2t[e]], 1);
    else             atomicAdd(&g_cnt_m2t[d_m2t[e]], 1);
}

// Phase 1: per-4096-chunk exclusive scan + chunk total. block=1024, int4/thread.
__global__ void scan_local_kernel() {
    int cb = blockIdx.x;
    const int* cnt; int* off; int n, chunk;
    if (cb < NCHC) { cnt = g_cnt_t2c; off = g_off_c; n = NCN; chunk = cb; }
    else           { cnt = g_cnt_t2m; off = g_off_m; n = NMN; chunk = cb - NCHC; }

    __shared__ int wsum[32];
    int t = threadIdx.x;
    int i = chunk * 4096 + t * 4;
    int4 v = make_int4(0, 0, 0, 0);
    if (i < n) v = ((const int4*)cnt)[i >> 2];
    int s0 = v.x, s1 = s0 + v.y, s2 = s1 + v.z, s3 = s2 + v.w;
    int x = s3;
    #pragma unroll
    for (int o = 1; o < 32; o <<= 1) {
        int y = __shfl_up_sync(0xffffffffu, x, o);
        if ((t & 31) >= o) x += y;
    }
    if ((t & 31) == 31) wsum[t >> 5] = x;
    __syncthreads();
    if (t < 32) {
        int w = wsum[t], xs = w;
        #pragma unroll
        for (int o = 1; o < 32; o <<= 1) {
            int y = __shfl_up_sync(0xffffffffu, xs, o);
            if (t >= o) xs += y;
        }
        if (t == 31) g_csum[cb] = xs;   // chunk total
        wsum[t] = xs - w;               // exclusive across warps
    }
    __syncthreads();
    int excl = wsum[t >> 5] + (x - s3);
    if (i < n) {
        int4 o4 = make_int4(excl, excl + s0, excl + s1, excl + s2);
        ((int4*)off)[i >> 2] = o4;
    }
}

// Phase 2: scan the 25 + 5 chunk totals (serial, tiny).
__global__ void scan_tops_kernel() {
    int t = threadIdx.x;
    if (t == 0) {
        int a = 0;
        for (int i = 0; i < NCHC; i++) { g_cbase[i] = a; a += g_csum[i]; }
    } else if (t == 1) {
        int a = 0;
        for (int i = 0; i < NCHM; i++) { g_cbase[NCHC + i] = a; a += g_csum[NCHC + i]; }
    }
}

// Phase 3: add chunk base.
__global__ void scan_addbase_kernel() {
    int cb = blockIdx.x;
    int bval = g_cbase[cb];
    if (bval == 0) return;
    int* off; int n, chunk;
    if (cb < NCHC) { off = g_off_c; n = NCN; chunk = cb; }
    else           { off = g_off_m; n = NMN; chunk = cb - NCHC; }
    int i = chunk * 4096 + threadIdx.x * 4;
    if (i < n) {
        int4 o = ((int4*)off)[i >> 2];
        o.x += bval; o.y += bval; o.z += bval; o.w += bval;
        ((int4*)off)[i >> 2] = o;
    }
}

// Fill both CSRs in one launch.
__global__ void fill_all_kernel(const int* __restrict__ src_c, const int* __restrict__ dst_c,
                                const int* __restrict__ src_m, const int* __restrict__ dst_m) {
    int i = blockIdx.x * blockDim.x + threadIdx.x;
    if (i >= 2 * NE) return;
    if (i < NE) {
        int d = dst_c[i];
        int p = atomicAdd(&g_cur_c[d], 1);
        g_eid_c[g_off_c[d] + p] = src_c[i];
    } else {
        int e = i - NE;
        int d = dst_m[e];
        int p = atomicAdd(&g_cur_m[d], 1);
        g_eid_m[g_off_m[d] + p] = src_m[e];
    }
}

// Gather-side aggregation, one warp per dst node, 8 rows in flight (MLP=8).
__global__ void agg_kernel(const float* __restrict__ feat) {
    int g = blockIdx.x * blockDim.x + threadIdx.x;
    int w = g >> 5, lane = g & 31;
    if (w >= NCN + NMN) return;
    const int *off, *cnt, *eid;
    float* agg;
    int node;
    if (w < NCN) { node = w;       off = g_off_c; cnt = g_cnt_t2c; eid = g_eid_c; agg = g_agg_c; }
    else         { node = w - NCN; off = g_off_m; cnt = g_cnt_t2m; eid = g_eid_m; agg = g_agg_m; }

    int o = off[node], c = cnt[node];
    const float4* f4 = (const float4*)feat;
    float4 acc = make_float4(0.f, 0.f, 0.f, 0.f);
    for (int b = 0; b < c; b += 32) {
        int m = min(32, c - b);
        int sreg = (lane < m) ? eid[o + b + lane] : 0;
        for (int j0 = 0; j0 < m; j0 += 8) {
            int jm = min(8, m - j0);
            float4 v[8];
            #pragma unroll
            for (int j = 0; j < 8; j++) {
                int s = __shfl_sync(0xffffffffu, sreg, j0 + j);
                if (j < jm) v[j] = __ldg(f4 + (size_t)s * (FIN / 4) + lane);
            }
            #pragma unroll
            for (int j = 0; j < 8; j++) {
                if (j < jm) {
                    acc.x += v[j].x; acc.y += v[j].y; acc.z += v[j].z; acc.w += v[j].w;
                }
            }
        }
    }
    ((float4*)agg)[(size_t)node * (FIN / 4) + lane] = acc;
}

__global__ void make_M_kernel(const float* __restrict__ W1c, const float* __restrict__ b1c,
                              const float* __restrict__ W1m, const float* __restrict__ b1m,
                              const float* __restrict__ Wf) {
    int t = threadIdx.x;  // 256 threads
    if (t < 128) {
        int k = t >> 1, o = t & 1;
        float s = 0.f;
        #pragma unroll
        for (int j = 0; j < FHID; j++) s += W1c[k * FHID + j] * Wf[j * 2 + o];
        g_M_c[k * 2 + o] = s;
    } else {
        int tt = t - 128;
        int k = tt >> 1, o = tt & 1;
        float s = 0.f;
        #pragma unroll
        for (int j = 0; j < FHID; j++) s += W1m[k * FHID + j] * Wf[j * 2 + o];
        g_M_m[k * 2 + o] = s;
    }
    if (t < 2) {
        float s = 0.f;
        #pragma unroll
        for (int j = 0; j < FHID; j++) s += b1c[j] * Wf[j * 2 + t];
        g_b2_c[t] = s;
    } else if (t < 4) {
        int o = t - 2;
        float s = 0.f;
        #pragma unroll
        for (int j = 0; j < FHID; j++) s += b1m[j] * Wf[j * 2 + o];
        g_b2_m[o] = s;
    }
}

// Fused layer0 for both relations. 64 nodes/block, 128 threads.
// Thread t: cg = t&7 (8 cols), ng = t>>3 (4 nodes). A in smem, W via L2.
// FMAs as packed fma.rn.f32x2 (col pairs).
__global__ void __launch_bounds__(128) layer0_kernel(
        const float* __restrict__ W0c, const float* __restrict__ b0c,
        const float* __restrict__ W0m, const float* __restrict__ b0m) {
    __shared__ float sA[64 * 129];

    bool isC = blockIdx.x < NBC;
    int base = (isC ? blockIdx.x : blockIdx.x - NBC) * 64;
    int n = isC ? NCN : NMN;
    const float* agg = isC ? g_agg_c : g_agg_m;
    const int*   cnt = isC ? g_cnt_t2c : g_cnt_t2m;
    const float* W0  = isC ? W0c : W0m;
    const float* b0  = isC ? b0c : b0m;
    const float* M   = isC ? g_M_c : g_M_m;
    const float* b2  = isC ? g_b2_c : g_b2_m;
    float*       pout = isC ? g_p_c : g_p_m;

    int t = threadIdx.x;
    // stage A: 64 rows x 128 (stride 129 -> conflict-free column reads)
    for (int i = t; i < 64 * FIN; i += 128) {
        int nd = i >> 7, k = i & 127;
        int gn = base + nd;
        sA[nd * 129 + k] = (gn < n) ? agg[(size_t)gn * FIN + k] : 0.f;
    }
    __syncthreads();

    int cg = t & 7;      // col group: cols [cg*8, cg*8+8)
    int ng = t >> 3;     // node group: nodes [ng*4, ng*4+4)

    unsigned long long acc[4][4];
    #pragma unroll
    for (int a = 0; a < 4; a++)
        #pragma unroll
        for (int p = 0; p < 4; p++) acc[a][p] = 0ull;

    const ulonglong2* Wp = (const ulonglong2*)W0;   // 4 col-pairs per ulonglong2... 2 pairs
    #pragma unroll 2
    for (int k = 0; k < FIN; k++) {
        float a0 = sA[(ng * 4 + 0) * 129 + k];
        float a1 = sA[(ng * 4 + 1) * 129 + k];
        float a2 = sA[(ng * 4 + 2) * 129 + k];
        float a3 = sA[(ng * 4 + 3) * 129 + k];
        unsigned long long aa0, aa1, aa2, aa3;
        asm("mov.b64 %0,{%1,%1};" : "=l"(aa0) : "f"(a0));
        asm("mov.b64 %0,{%1,%1};" : "=l"(aa1) : "f"(a1));
        asm("mov.b64 %0,{%1,%1};" : "=l"(aa2) : "f"(a2));
        asm("mov.b64 %0,{%1,%1};" : "=l"(aa3) : "f"(a3));
        ulonglong2 wlo = __ldg(Wp + (size_t)k * 16 + cg * 2);      // cols cg*8+0..3
        ulonglong2 whi = __ldg(Wp + (size_t)k * 16 + cg * 2 + 1);  // cols cg*8+4..7
        #define FMA2(A, B, C) asm("fma.rn.f32x2 %0,%1,%2,%0;" : "+l"(A) : "l"(B), "l"(C))
        FMA2(acc[0][0], aa0, wlo.x); FMA2(acc[0][1], aa0, wlo.y);
        FMA2(acc[0][2], aa0, whi.x); FMA2(acc[0][3], aa0, whi.y);
        FMA2(acc[1][0], aa1, wlo.x); FMA2(acc[1][1], aa1, wlo.y);
        FMA2(acc[1][2], aa1, whi.x); FMA2(acc[1][3], aa1, whi.y);
        FMA2(acc[2][0], aa2, wlo.x); FMA2(acc[2][1], aa2, wlo.y);
        FMA2(acc[2][2], aa2, whi.x); FMA2(acc[2][3], aa2, whi.y);
        FMA2(acc[3][0], aa3, wlo.x); FMA2(acc[3][1], aa3, wlo.y);
        FMA2(acc[3][2], aa3, whi.x); FMA2(acc[3][3], aa3, whi.y);
        #undef FMA2
    }

    // epilogue: per node -> h0 = lrelu(z/c + b0), p = h0@M + b2, reduce over 8 cg lanes
    #pragma unroll
    for (int a = 0; a < 4; a++) {
        int gn = base + ng * 4 + a;
        int c = (gn < n) ? cnt[gn] : 0;
        float p0 = 0.f, p1 = 0.f;
        if (c > 0) {
            float inv = 1.f / (float)c;
            #pragma unroll
            for (int p = 0; p < 4; p++) {
                float zlo, zhi;
                asm("mov.b64 {%0,%1},%2;" : "=f"(zlo), "=f"(zhi) : "l"(acc[a][p]));
                int col = cg * 8 + 2 * p;
                float h = zlo * inv + b0[col];
                h = (h > 0.f) ? h : 0.01f * h;
                p0 += h * M[col * 2];
                p1 += h * M[col * 2 + 1];
                h = zhi * inv + b0[col + 1];
                h = (h > 0.f) ? h : 0.01f * h;
                p0 += h * M[(col + 1) * 2];
                p1 += h * M[(col + 1) * 2 + 1];
            }
        }
        #pragma unroll
        for (int off = 4; off; off >>= 1) {
            p0 += __shfl_down_sync(0xffffffffu, p0, off, 8);
            p1 += __shfl_down_sync(0xffffffffu, p1, off, 8);
        }
        if (cg == 0 && gn < n) {
            pout[gn * 2]     = p0 + b2[0];
            pout[gn * 2 + 1] = p1 + b2[1];
        }
    }
}

__global__ void out_init_kernel(float* __restrict__ out, const float* __restrict__ bf) {
    int i = blockIdx.x * blockDim.x + threadIdx.x;
    if (i < NTN) ((float2*)out)[i] = make_float2(bf[0], bf[1]);
}

// Both relations fused.
__global__ void scatter_all_kernel(const int* __restrict__ src_c, const int* __restrict__ dst_c,
                                   const int* __restrict__ src_m, const int* __restrict__ dst_m,
                                   float* __restrict__ out) {
    int i = blockIdx.x * blockDim.x + threadIdx.x;
    if (i >= 2 * NE) return;
    int s, d;
    const float* p;
    const int* cnt;
    if (i < NE) { s = src_c[i]; d = dst_c[i]; p = g_p_c; cnt = g_cnt_c2t; }
    else        { int e = i - NE; s = src_m[e]; d = dst_m[e]; p = g_p_m; cnt = g_cnt_m2t; }
    float inv = 1.f / (float)cnt[d];
    float a = p[2 * s] * inv;
    float b = p[2 * s + 1] * inv;
    float* ap = out + 2 * (size_t)d;
    asm volatile("red.global.add.v2.f32 [%0], {%1,%2};"
                 :: "l"(ap), "f"(a), "f"(b) : "memory");
}

// ---------------- launch ----------------
extern "C" void kernel_launch(void* const* d_in, const int* in_sizes, int n_in,
                              void* d_out, int out_size) {
    const float* feat    = (const float*)d_in[0];
    const int* src_c2t   = (const int*)d_in[3];
    const int* dst_c2t   = (const int*)d_in[4];
    const int* src_m2t   = (const int*)d_in[5];
    const int* dst_m2t   = (const int*)d_in[6];
    const int* src_t2c   = (const int*)d_in[7];
    const int* dst_t2c   = (const int*)d_in[8];
    const int* src_t2m   = (const int*)d_in[9];
    const int* dst_t2m   = (const int*)d_in[10];
    const float* W1_c2t  = (const float*)d_in[13];
    const float* b1_c2t  = (const float*)d_in[14];
    const float* W1_m2t  = (const float*)d_in[17];
    const float* b1_m2t  = (const float*)d_in[18];
    const float* W0_t2c  = (const float*)d_in[19];
    const float* b0_t2c  = (const float*)d_in[20];
    const float* W0_t2m  = (const float*)d_in[23];
    const float* b0_t2m  = (const float*)d_in[24];
    const float* Wf      = (const float*)d_in[27];
    const float* bf      = (const float*)d_in[28];
    float* out = (float*)d_out;

    const int TB = 256;

    init_kernel<<<1024, TB>>>();
    count_all_kernel<<<(4 * NE + TB - 1) / TB, TB>>>(dst_t2c, dst_t2m, dst_c2t, dst_m2t);
    scan_local_kernel<<<NCHC + NCHM, 1024>>>();
    scan_tops_kernel<<<1, 32>>>();
    scan_addbase_kernel<<<NCHC + NCHM, 1024>>>();
    fill_all_kernel<<<(2 * NE + TB - 1) / TB, TB>>>(src_t2c, dst_t2c, src_t2m, dst_t2m);
    make_M_kernel<<<1, 256>>>(W1_c2t, b1_c2t, W1_m2t, b1_m2t, Wf);

    agg_kernel<<<((NCN + NMN) * 32 + TB - 1) / TB, TB>>>(feat);
    layer0_kernel<<<NBC + NBM, 128>>>(W0_t2c, b0_t2c, W0_t2m, b0_t2m);

    out_init_kernel<<<(NTN + TB - 1) / TB, TB>>>(out, bf);
    scatter_all_kernel<<<(2 * NE + TB - 1) / TB, TB>>>(src_c2t, dst_c2t, src_m2t, dst_m2t, out);
}

// round 7
// speedup vs baseline: 2.0814x; 1.2032x over previous
#include <cuda_runtime.h>

#define NTN 500000
#define NCN 100000
#define NMN 20000
#define NE  500000
#define FIN 128
#define FHID 64

#define NCHC 25          // ceil(NCN/4096)
#define NCHM 5           // ceil(NMN/4096)
#define NBC 1563         // ceil(NCN/64)
#define NBM 313          // ceil(NMN/64)
#define SASTR 132        // smem A stride (floats): 132*4=528 B, 16B-aligned rows

// ---------------- device scratch ----------------
__device__ float g_p_c[NCN * 2];
__device__ float g_p_m[NMN * 2];
__device__ int   g_cnt_t2c[NCN];
__device__ int   g_cnt_t2m[NMN];
__device__ int   g_cnt_c2t[NTN];
__device__ int   g_cnt_m2t[NTN];
__device__ int   g_off_c[NCN];
__device__ int   g_off_m[NMN];
__device__ int   g_cur_c[NCN];
__device__ int   g_cur_m[NMN];
__device__ int   g_eid_c[NE];
__device__ int   g_eid_m[NE];
__device__ int   g_csum[NCHC + NCHM];
__device__ int   g_cbase[NCHC + NCHM];
__device__ float g_M_c[FHID * 2];
__device__ float g_M_m[FHID * 2];
__device__ float g_b2_c[2];
__device__ float g_b2_m[2];

// ---------------- kernels ----------------

__global__ void initA_kernel() {            // CSR-side counters
    int i = blockIdx.x * blockDim.x + threadIdx.x;
    int stride = gridDim.x * blockDim.x;
    for (int j = i; j < NCN; j += stride) g_cnt_t2c[j] = 0;
    for (int j = i; j < NMN; j += stride) g_cnt_t2m[j] = 0;
}

__global__ void initB_kernel() {            // scatter-side counters
    int i = blockIdx.x * blockDim.x + threadIdx.x;
    int stride = gridDim.x * blockDim.x;
    for (int j = i; j < NTN; j += stride) { g_cnt_c2t[j] = 0; g_cnt_m2t[j] = 0; }
}

__global__ void countA_kernel(const int* __restrict__ d_t2c, const int* __restrict__ d_t2m) {
    int i = blockIdx.x * blockDim.x + threadIdx.x;
    if (i >= 2 * NE) return;
    if (i < NE) atomicAdd(&g_cnt_t2c[d_t2c[i]], 1);
    else        atomicAdd(&g_cnt_t2m[d_t2m[i - NE]], 1);
}

__global__ void countB_kernel(const int* __restrict__ d_c2t, const int* __restrict__ d_m2t) {
    int i = blockIdx.x * blockDim.x + threadIdx.x;
    if (i >= 2 * NE) return;
    if (i < NE) atomicAdd(&g_cnt_c2t[d_c2t[i]], 1);
    else        atomicAdd(&g_cnt_m2t[d_m2t[i - NE]], 1);
}

// Phase 1: per-4096-chunk exclusive scan + chunk total. block=1024, int4/thread.
__global__ void scan_local_kernel() {
    int cb = blockIdx.x;
    const int* cnt; int* off; int n, chunk;
    if (cb < NCHC) { cnt = g_cnt_t2c; off = g_off_c; n = NCN; chunk = cb; }
    else           { cnt = g_cnt_t2m; off = g_off_m; n = NMN; chunk = cb - NCHC; }

    __shared__ int wsum[32];
    int t = threadIdx.x;
    int i = chunk * 4096 + t * 4;
    int4 v = make_int4(0, 0, 0, 0);
    if (i < n) v = ((const int4*)cnt)[i >> 2];
    int s0 = v.x, s1 = s0 + v.y, s2 = s1 + v.z, s3 = s2 + v.w;
    int x = s3;
    #pragma unroll
    for (int o = 1; o < 32; o <<= 1) {
        int y = __shfl_up_sync(0xffffffffu, x, o);
        if ((t & 31) >= o) x += y;
    }
    if ((t & 31) == 31) wsum[t >> 5] = x;
    __syncthreads();
    if (t < 32) {
        int w = wsum[t], xs = w;
        #pragma unroll
        for (int o = 1; o < 32; o <<= 1) {
            int y = __shfl_up_sync(0xffffffffu, xs, o);
            if (t >= o) xs += y;
        }
        if (t == 31) g_csum[cb] = xs;
        wsum[t] = xs - w;
    }
    __syncthreads();
    int excl = wsum[t >> 5] + (x - s3);
    if (i < n) {
        int4 o4 = make_int4(excl, excl + s0, excl + s1, excl + s2);
        ((int4*)off)[i >> 2] = o4;
    }
}

// Phase 2: warp-parallel scan of chunk totals (25 + 5).
__global__ void scan_tops_kernel() {
    int t = threadIdx.x;        // 64 threads: warp0 -> C chunks, warp1 -> M chunks
    int w = t >> 5, l = t & 31;
    int n = w ? NCHM : NCHC;
    int base = w ? NCHC : 0;
    int v = (l < n) ? g_csum[base + l] : 0;
    int x = v;
    #pragma unroll
    for (int o = 1; o < 32; o <<= 1) {
        int y = __shfl_up_sync(0xffffffffu, x, o);
        if (l >= o) x += y;
    }
    if (l < n) g_cbase[base + l] = x - v;
}

// Phase 3: add chunk base; also initialize cur = off (fill cursor).
__global__ void scan_addbase_kernel() {
    int cb = blockIdx.x;
    int bval = g_cbase[cb];
    int* off; int* cur; int n, chunk;
    if (cb < NCHC) { off = g_off_c; cur = g_cur_c; n = NCN; chunk = cb; }
    else           { off = g_off_m; cur = g_cur_m; n = NMN; chunk = cb - NCHC; }
    int i = chunk * 4096 + threadIdx.x * 4;
    if (i < n) {
        int4 o = ((int4*)off)[i >> 2];
        o.x += bval; o.y += bval; o.z += bval; o.w += bval;
        ((int4*)off)[i >> 2] = o;
        ((int4*)cur)[i >> 2] = o;
    }
}

// Fill both CSRs in one launch; cur doubles as slot cursor (starts at off).
__global__ void fill_all_kernel(const int* __restrict__ src_c, const int* __restrict__ dst_c,
                                const int* __restrict__ src_m, const int* __restrict__ dst_m) {
    int i = blockIdx.x * blockDim.x + threadIdx.x;
    if (i >= 2 * NE) return;
    if (i < NE) {
        int p = atomicAdd(&g_cur_c[dst_c[i]], 1);
        g_eid_c[p] = src_c[i];
    } else {
        int e = i - NE;
        int p = atomicAdd(&g_cur_m[dst_m[e]], 1);
        g_eid_m[p] = src_m[e];
    }
}

__global__ void make_M_kernel(const float* __restrict__ W1c, const float* __restrict__ b1c,
                              const float* __restrict__ W1m, const float* __restrict__ b1m,
                              const float* __restrict__ Wf) {
    int t = threadIdx.x;  // 256 threads
    if (t < 128) {
        int k = t >> 1, o = t & 1;
        float s = 0.f;
        #pragma unroll
        for (int j = 0; j < FHID; j++) s += W1c[k * FHID + j] * Wf[j * 2 + o];
        g_M_c[k * 2 + o] = s;
    } else {
        int tt = t - 128;
        int k = tt >> 1, o = tt & 1;
        float s = 0.f;
        #pragma unroll
        for (int j = 0; j < FHID; j++) s += W1m[k * FHID + j] * Wf[j * 2 + o];
        g_M_m[k * 2 + o] = s;
    }
    if (t < 2) {
        float s = 0.f;
        #pragma unroll
        for (int j = 0; j < FHID; j++) s += b1c[j] * Wf[j * 2 + t];
        g_b2_c[t] = s;
    } else if (t < 4) {
        int o = t - 2;
        float s = 0.f;
        #pragma unroll
        for (int j = 0; j < FHID; j++) s += b1m[j] * Wf[j * 2 + o];
        g_b2_m[o] = s;
    }
}

// Fused gather-aggregate + layer0 GEMM + projection. 64 nodes/block, 256 threads.
// Merchant blocks scheduled FIRST (heavier: avg degree 25 vs 5) to avoid a slow tail.
// Phase 1: warp w aggregates nodes w*8..w*8+7 into smem (MLP=8 gather).
// Phase 2: thread (cg=t&7, ng=t>>3) computes 2 nodes (ng, ng+32) x 8 cols via fma.f32x2.
__global__ void __launch_bounds__(256) aggmm_kernel(
        const float* __restrict__ feat,
        const float* __restrict__ W0c, const float* __restrict__ b0c,
        const float* __restrict__ W0m, const float* __restrict__ b0m) {
    __shared__ float sA[64 * SASTR];

    bool isC = blockIdx.x >= NBM;
    int base = (isC ? blockIdx.x - NBM : blockIdx.x) * 64;
    int n = isC ? NCN : NMN;
    const int*   off = isC ? g_off_c : g_off_m;
    const int*   cnt = isC ? g_cnt_t2c : g_cnt_t2m;
    const int*   eid = isC ? g_eid_c : g_eid_m;
    const float* W0  = isC ? W0c : W0m;
    const float* b0  = isC ? b0c : b0m;
    const float* M   = isC ? g_M_c : g_M_m;
    const float* b2  = isC ? g_b2_c : g_b2_m;
    float*       pout = isC ? g_p_c : g_p_m;

    int t = threadIdx.x;
    int w = t >> 5, lane = t & 31;
    const float4* f4 = (const float4*)feat;

    // ---- Phase 1: gather-aggregate into smem ----
    #pragma unroll 1
    for (int i = 0; i < 8; i++) {
        int nd = w * 8 + i;
        int gn = base + nd;
        float4 acc = make_float4(0.f, 0.f, 0.f, 0.f);
        if (gn < n) {
            int o = off[gn], c = cnt[gn];
            for (int b = 0; b < c; b += 32) {
                int m = min(32, c - b);
                int sreg = (lane < m) ? eid[o + b + lane] : 0;
                for (int j0 = 0; j0 < m; j0 += 8) {
                    int jm = min(8, m - j0);
                    float4 v[8];
                    #pragma unroll
                    for (int j = 0; j < 8; j++) {
                        int s = __shfl_sync(0xffffffffu, sreg, j0 + j);
                        if (j < jm) v[j] = __ldg(f4 + (size_t)s * (FIN / 4) + lane);
                    }
                    #pragma unroll
                    for (int j = 0; j < 8; j++) {
                        if (j < jm) {
                            acc.x += v[j].x; acc.y += v[j].y; acc.z += v[j].z; acc.w += v[j].w;
                        }
                    }
                }
            }
        }
        ((float4*)(sA + nd * SASTR))[lane] = acc;    // 528B rows, 16B aligned
    }
    __syncthreads();

    // ---- Phase 2: GEMM + epilogue ----
    int cg = t & 7;       // col group: cols [cg*8, cg*8+8)
    int ng = t >> 3;      // 0..31; this thread owns nodes ng and ng+32

    unsigned long long acc[2][4];
    #pragma unroll
    for (int a = 0; a < 2; a++)
        #pragma unroll
        for (int p = 0; p < 4; p++) acc[a][p] = 0ull;

    const ulonglong2* Wp = (const ulonglong2*)W0;
    #pragma unroll 2
    for (int k = 0; k < FIN; k++) {
        float a0 = sA[ng * SASTR + k];
        float a1 = sA[(ng + 32) * SASTR + k];
        unsigned long long aa0, aa1;
        asm("mov.b64 %0,{%1,%1};" : "=l"(aa0) : "f"(a0));
        asm("mov.b64 %0,{%1,%1};" : "=l"(aa1) : "f"(a1));
        ulonglong2 wlo = __ldg(Wp + (size_t)k * 16 + cg * 2);
        ulonglong2 whi = __ldg(Wp + (size_t)k * 16 + cg * 2 + 1);
        #define FMA2(A, B, C) asm("fma.rn.f32x2 %0,%1,%2,%0;" : "+l"(A) : "l"(B), "l"(C))
        FMA2(acc[0][0], aa0, wlo.x); FMA2(acc[0][1], aa0, wlo.y);
        FMA2(acc[0][2], aa0, whi.x); FMA2(acc[0][3], aa0, whi.y);
        FMA2(acc[1][0], aa1, wlo.x); FMA2(acc[1][1], aa1, wlo.y);
        FMA2(acc[1][2], aa1, whi.x); FMA2(acc[1][3], aa1, whi.y);
        #undef FMA2
    }

    #pragma unroll
    for (int a = 0; a < 2; a++) {
        int gn = base + ng + a * 32;
        int c = (gn < n) ? cnt[gn] : 0;
        float p0 = 0.f, p1 = 0.f;
        if (c > 0) {
            float inv = 1.f / (float)c;
            #pragma unroll
            for (int p = 0; p < 4; p++) {
                float zlo, zhi;
                asm("mov.b64 {%0,%1},%2;" : "=f"(zlo), "=f"(zhi) : "l"(acc[a][p]));
                int col = cg * 8 + 2 * p;
                float h = zlo * inv + b0[col];
                h = (h > 0.f) ? h : 0.01f * h;
                p0 += h * M[col * 2];
                p1 += h * M[col * 2 + 1];
                h = zhi * inv + b0[col + 1];
                h = (h > 0.f) ? h : 0.01f * h;
                p0 += h * M[(col + 1) * 2];
                p1 += h * M[(col + 1) * 2 + 1];
            }
        }
        #pragma unroll
        for (int o = 4; o; o >>= 1) {
            p0 += __shfl_down_sync(0xffffffffu, p0, o, 8);
            p1 += __shfl_down_sync(0xffffffffu, p1, o, 8);
        }
        if (cg == 0 && gn < n) {
            pout[gn * 2]     = p0 + b2[0];
            pout[gn * 2 + 1] = p1 + b2[1];
        }
    }
}

__global__ void out_init_kernel(float* __restrict__ out, const float* __restrict__ bf) {
    int i = blockIdx.x * blockDim.x + threadIdx.x;
    if (i < NTN) ((float2*)out)[i] = make_float2(bf[0], bf[1]);
}

__global__ void scatter_all_kernel(const int* __restrict__ src_c, const int* __restrict__ dst_c,
                                   const int* __restrict__ src_m, const int* __restrict__ dst_m,
                                   float* __restrict__ out) {
    int i = blockIdx.x * blockDim.x + threadIdx.x;
    if (i >= 2 * NE) return;
    int s, d;
    const float* p;
    const int* cnt;
    if (i < NE) { s = src_c[i]; d = dst_c[i]; p = g_p_c; cnt = g_cnt_c2t; }
    else        { int e = i - NE; s = src_m[e]; d = dst_m[e]; p = g_p_m; cnt = g_cnt_m2t; }
    float inv = 1.f / (float)cnt[d];
    float a = p[2 * s] * inv;
    float b = p[2 * s + 1] * inv;
    float* ap = out + 2 * (size_t)d;
    asm volatile("red.global.add.v2.f32 [%0], {%1,%2};"
                 :: "l"(ap), "f"(a), "f"(b) : "memory");
}

// ---------------- launch ----------------
extern "C" void kernel_launch(void* const* d_in, const int* in_sizes, int n_in,
                              void* d_out, int out_size) {
    const float* feat    = (const float*)d_in[0];
    const int* src_c2t   = (const int*)d_in[3];
    const int* dst_c2t   = (const int*)d_in[4];
    const int* src_m2t   = (const int*)d_in[5];
    const int* dst_m2t   = (const int*)d_in[6];
    const int* src_t2c   = (const int*)d_in[7];
    const int* dst_t2c   = (const int*)d_in[8];
    const int* src_t2m   = (const int*)d_in[9];
    const int* dst_t2m   = (const int*)d_in[10];
    const float* W1_c2t  = (const float*)d_in[13];
    const float* b1_c2t  = (const float*)d_in[14];
    const float* W1_m2t  = (const float*)d_in[17];
    const float* b1_m2t  = (const float*)d_in[18];
    const float* W0_t2c  = (const float*)d_in[19];
    const float* b0_t2c  = (const float*)d_in[20];
    const float* W0_t2m  = (const float*)d_in[23];
    const float* b0_t2m  = (const float*)d_in[24];
    const float* Wf      = (const float*)d_in[27];
    const float* bf      = (const float*)d_in[28];
    float* out = (float*)d_out;

    const int TB = 256;

    // Side stream for DAG-independent work (host objects only; no device alloc).
    cudaStream_t s2;
    cudaStreamCreateWithFlags(&s2, cudaStreamNonBlocking);
    cudaEvent_t evF, evB;
    cudaEventCreateWithFlags(&evF, cudaEventDisableTiming);
    cudaEventCreateWithFlags(&evB, cudaEventDisableTiming);

    cudaEventRecord(evF, 0);
    cudaStreamWaitEvent(s2, evF, 0);

    // stream B: scatter-side counts + output init + fused-weight precompute
    initB_kernel<<<1024, TB, 0, s2>>>();
    countB_kernel<<<(2 * NE + TB - 1) / TB, TB, 0, s2>>>(dst_c2t, dst_m2t);
    out_init_kernel<<<(NTN + TB - 1) / TB, TB, 0, s2>>>(out, bf);
    make_M_kernel<<<1, 256, 0, s2>>>(W1_c2t, b1_c2t, W1_m2t, b1_m2t, Wf);
    cudaEventRecord(evB, s2);

    // stream A (default): CSR build -> fused agg+GEMM -> scatter
    initA_kernel<<<512, TB>>>();
    countA_kernel<<<(2 * NE + TB - 1) / TB, TB>>>(dst_t2c, dst_t2m);
    scan_local_kernel<<<NCHC + NCHM, 1024>>>();
    scan_tops_kernel<<<1, 64>>>();
    scan_addbase_kernel<<<NCHC + NCHM, 1024>>>();
    fill_all_kernel<<<(2 * NE + TB - 1) / TB, TB>>>(src_t2c, dst_t2c, src_t2m, dst_t2m);

    cudaStreamWaitEvent((cudaStream_t)0, evB, 0);   // need make_M before aggmm, out_init/counts before scatter
    aggmm_kernel<<<NBC + NBM, 256>>>(feat, W0_t2c, b0_t2c, W0_t2m, b0_t2m);
    scatter_all_kernel<<<(2 * NE + TB - 1) / TB, TB>>>(src_c2t, dst_c2t, src_m2t, dst_m2t, out);
}